// round 1
// baseline (speedup 1.0000x reference)
#include <cuda_runtime.h>
#include <math.h>

#define B_  4
#define T_  2048
#define D_  512
#define H_  8
#define P_  16
#define DH_ 64
#define C_  512
#define HF_ 64
#define WF_ 64
#define HW_ (HF_*WF_)
#define RADIUS_ 0.08f

// ---- scratch (no allocations allowed) ----
__device__ float g_v  [(size_t)B_*HW_*D_];      // [B, HW, D]  d = h*64+dh contiguous
__device__ float g_off[(size_t)B_*T_*H_*P_*2];  // [B*T, H, P, 2]
__device__ float g_w  [(size_t)B_*T_*H_*P_];    // [B*T, H, P]
__device__ float g_ctx[(size_t)B_*T_*D_];       // [B*T, D]

#define BM 64
#define BN 64
#define BK 16
#define PADM (BM+4)
#define PADN (BN+4)

// C[b, m, n] = sum_k A[b, k, m] * B[k, n]       (A is k-major: fmap)
__global__ void gemm_tn(const float* __restrict__ A, const float* __restrict__ Bm,
                        float* __restrict__ C, int M, int N, int K)
{
    __shared__ float As[BK][PADM];
    __shared__ float Bs[BK][PADN];
    const int bz = blockIdx.z;
    const float* Ab = A + (size_t)bz * K * M;
    float*       Cb = C + (size_t)bz * M * N;
    const int m0 = blockIdx.x * BM, n0 = blockIdx.y * BN;
    const int tid = threadIdx.x;
    const int row  = tid >> 4;          // 0..15
    const int col4 = (tid & 15) << 2;   // 0..60
    const int ty = tid >> 4, tx = tid & 15;

    float acc[4][4] = {};
    for (int k0 = 0; k0 < K; k0 += BK) {
        *(float4*)&As[row][col4] = *(const float4*)&Ab[(size_t)(k0 + row) * M + m0 + col4];
        *(float4*)&Bs[row][col4] = *(const float4*)&Bm[(size_t)(k0 + row) * N + n0 + col4];
        __syncthreads();
        #pragma unroll
        for (int k = 0; k < BK; k++) {
            float4 a = *(const float4*)&As[k][ty << 2];
            float4 b = *(const float4*)&Bs[k][tx << 2];
            float av[4] = {a.x, a.y, a.z, a.w};
            float bv[4] = {b.x, b.y, b.z, b.w};
            #pragma unroll
            for (int i = 0; i < 4; i++)
                #pragma unroll
                for (int j = 0; j < 4; j++)
                    acc[i][j] += av[i] * bv[j];
        }
        __syncthreads();
    }
    #pragma unroll
    for (int i = 0; i < 4; i++)
        #pragma unroll
        for (int j = 0; j < 4; j++)
            Cb[(size_t)(m0 + (ty << 2) + i) * N + n0 + (tx << 2) + j] = acc[i][j];
}

// C[m, n] = sum_k A[m, k] * B[k, n] + bias[n]   (row-major A)
__global__ void gemm_nn(const float* __restrict__ A, const float* __restrict__ Bm,
                        const float* __restrict__ bias, float* __restrict__ C,
                        int M, int N, int K)
{
    __shared__ float As[BK][PADM];
    __shared__ float Bs[BK][PADN];
    const int m0 = blockIdx.x * BM, n0 = blockIdx.y * BN;
    const int tid = threadIdx.x;
    const int am = tid >> 2;            // 0..63
    const int ak = (tid & 3) << 2;      // 0,4,8,12
    const int brow = tid >> 4, bcol = (tid & 15) << 2;
    const int ty = tid >> 4, tx = tid & 15;

    float acc[4][4] = {};
    for (int k0 = 0; k0 < K; k0 += BK) {
        float4 av = *(const float4*)&A[(size_t)(m0 + am) * K + k0 + ak];
        As[ak + 0][am] = av.x;
        As[ak + 1][am] = av.y;
        As[ak + 2][am] = av.z;
        As[ak + 3][am] = av.w;
        *(float4*)&Bs[brow][bcol] = *(const float4*)&Bm[(size_t)(k0 + brow) * N + n0 + bcol];
        __syncthreads();
        #pragma unroll
        for (int k = 0; k < BK; k++) {
            float4 a = *(const float4*)&As[k][ty << 2];
            float4 b = *(const float4*)&Bs[k][tx << 2];
            float avv[4] = {a.x, a.y, a.z, a.w};
            float bvv[4] = {b.x, b.y, b.z, b.w};
            #pragma unroll
            for (int i = 0; i < 4; i++)
                #pragma unroll
                for (int j = 0; j < 4; j++)
                    acc[i][j] += avv[i] * bvv[j];
        }
        __syncthreads();
    }
    #pragma unroll
    for (int i = 0; i < 4; i++)
        #pragma unroll
        for (int j = 0; j < 4; j++)
            C[(size_t)(m0 + (ty << 2) + i) * N + n0 + (tx << 2) + j] =
                acc[i][j] + bias[n0 + (tx << 2) + j];
}

// One block per (b,t). Warp w = head h. Softmax over P=16, bilinear gather,
// accumulate ctx[b,t, h*64 + dh].
__global__ void sample_kernel(const float* __restrict__ ref_xy)
{
    const int bt = blockIdx.x;                 // 0..B*T-1
    const int b  = bt >> 11;                   // T_=2048
    const int h  = threadIdx.x >> 5;
    const int lane = threadIdx.x & 31;

    const float* vb = g_v + (size_t)b * HW_ * D_;
    const float rx = ref_xy[(size_t)bt * 2 + 0];
    const float ry = ref_xy[(size_t)bt * 2 + 1];

    const size_t base_w = ((size_t)bt * H_ + h) * P_;

    // lanes 0..15 hold point p = lane
    float wv = -INFINITY, ox = 0.f, oy = 0.f;
    if (lane < P_) {
        wv = g_w[base_w + lane];
        ox = g_off[(base_w + lane) * 2 + 0];
        oy = g_off[(base_w + lane) * 2 + 1];
    }
    // softmax over groups of 16 lanes (lanes>=16 carry -inf / 0)
    float m = wv;
    #pragma unroll
    for (int o = 8; o >= 1; o >>= 1) m = fmaxf(m, __shfl_xor_sync(0xffffffffu, m, o));
    float e = (lane < P_) ? __expf(wv - m) : 0.f;
    float s = e;
    #pragma unroll
    for (int o = 8; o >= 1; o >>= 1) s += __shfl_xor_sync(0xffffffffu, s, o);
    const float aw = (lane < P_) ? (e / s) : 0.f;

    // bilinear setup on lane p
    const float ix = (rx + RADIUS_ * ox) * (float)(WF_ - 1);
    const float iy = (ry + RADIUS_ * oy) * (float)(HF_ - 1);
    const float fx0 = floorf(ix), fy0 = floorf(iy);
    const int   x0 = (int)fx0,   y0 = (int)fy0;
    const float fx = ix - fx0,   fy = iy - fy0;

    int   idxc[4];
    float wc[4];
    {
        const int x1 = x0 + 1, y1 = y0 + 1;
        const int xs[4] = {x0, x1, x0, x1};
        const int ys[4] = {y0, y0, y1, y1};
        const float ww[4] = {(1.f - fx) * (1.f - fy), fx * (1.f - fy),
                             (1.f - fx) * fy,         fx * fy};
        #pragma unroll
        for (int c = 0; c < 4; c++) {
            const bool valid = (xs[c] >= 0) & (xs[c] < WF_) & (ys[c] >= 0) & (ys[c] < HF_);
            const int xc = min(max(xs[c], 0), WF_ - 1);
            const int yc = min(max(ys[c], 0), HF_ - 1);
            idxc[c] = yc * WF_ + xc;
            wc[c]   = valid ? (ww[c] * aw) : 0.f;
        }
    }

    float acc0 = 0.f, acc1 = 0.f;
    const int hbase = h * DH_;
    #pragma unroll 4
    for (int p = 0; p < P_; p++) {
        #pragma unroll
        for (int c = 0; c < 4; c++) {
            const int   idx = __shfl_sync(0xffffffffu, idxc[c], p);
            const float w   = __shfl_sync(0xffffffffu, wc[c],   p);
            if (w != 0.f) {                       // warp-uniform branch
                const float* vp = vb + (size_t)idx * D_ + hbase;
                acc0 += w * vp[lane];
                acc1 += w * vp[lane + 32];
            }
        }
    }
    float* cp = g_ctx + (size_t)bt * D_ + hbase;
    cp[lane]      = acc0;
    cp[lane + 32] = acc1;
}

extern "C" void kernel_launch(void* const* d_in, const int* in_sizes, int n_in,
                              void* d_out, int out_size)
{
    const float* q      = (const float*)d_in[0];
    const float* fmap   = (const float*)d_in[1];
    const float* ref_xy = (const float*)d_in[2];
    const float* Wv     = (const float*)d_in[3];
    const float* W_off  = (const float*)d_in[4];
    const float* b_off  = (const float*)d_in[5];
    const float* W_w    = (const float*)d_in[6];
    const float* b_w    = (const float*)d_in[7];
    const float* W_out  = (const float*)d_in[8];
    const float* b_out  = (const float*)d_in[9];
    float* out = (float*)d_out;

    float *v, *offb, *wb, *ctx;
    cudaGetSymbolAddress((void**)&v,    g_v);
    cudaGetSymbolAddress((void**)&offb, g_off);
    cudaGetSymbolAddress((void**)&wb,   g_w);
    cudaGetSymbolAddress((void**)&ctx,  g_ctx);

    const int M = B_ * T_;  // 8192

    // K1: v[b,hw,d] = sum_c fmap[b,c,hw] * Wv[c,d]
    gemm_tn<<<dim3(HW_ / BM, D_ / BN, B_), 256>>>(fmap, Wv, v, HW_, D_, C_);

    // K2: off = q @ W_off + b_off ; w = q @ W_w + b_w
    gemm_nn<<<dim3(M / BM, (H_ * P_ * 2) / BN), 256>>>(q, W_off, b_off, offb, M, H_ * P_ * 2, D_);
    gemm_nn<<<dim3(M / BM, (H_ * P_) / BN),     256>>>(q, W_w,   b_w,   wb,   M, H_ * P_,     D_);

    // K3: softmax + bilinear gather -> ctx
    sample_kernel<<<M, H_ * 32>>>(ref_xy);

    // K4: out = ctx @ W_out + b_out
    gemm_nn<<<dim3(M / BM, D_ / BN), 256>>>(ctx, W_out, b_out, out, M, D_, D_);
}

// round 5
// speedup vs baseline: 1.6993x; 1.6993x over previous
#include <cuda_runtime.h>
#include <cuda_bf16.h>
#include <math.h>
#include <stdint.h>

#define B_  4
#define T_  2048
#define D_  512
#define H_  8
#define P_  16
#define DH_ 64
#define C_  512
#define HF_ 64
#define WF_ 64
#define HW_ (HF_*WF_)
#define RADIUS_ 0.08f
#define M_BT (B_*T_)          // 8192
#define NQ_ (H_*P_*2 + H_*P_) // 384

// ---- scratch (no allocations allowed) ----
__device__ float g_v    [(size_t)B_*HW_*D_];     // [B, HW, D]
__device__ float g_proj [(size_t)M_BT*NQ_];      // [B*T, 384]: 0..255 off, 256..383 w
__device__ float g_ctx  [(size_t)M_BT*D_];       // [B*T, D]
__device__ float g_fmapT[(size_t)B_*HW_*C_];     // [B, HW, C]
__device__ float g_WvT  [(size_t)D_*C_];
__device__ float g_WoutT[(size_t)D_*D_];
__device__ float g_WqT  [(size_t)NQ_*D_];
__device__ float g_bq   [NQ_];

// ============================================================
// Transposes
// ============================================================
__global__ void transpose_kernel(const float* __restrict__ in, float* __restrict__ out,
                                 int R, int C) {
    __shared__ float tile[32][33];
    const size_t bo = (size_t)blockIdx.z * R * C;
    const int c0 = blockIdx.x * 32, r0 = blockIdx.y * 32;
    const int tx = threadIdx.x, ty = threadIdx.y;
    #pragma unroll
    for (int i = 0; i < 32; i += 8)
        tile[ty + i][tx] = in[bo + (size_t)(r0 + ty + i) * C + c0 + tx];
    __syncthreads();
    #pragma unroll
    for (int i = 0; i < 32; i += 8)
        out[bo + (size_t)(c0 + ty + i) * R + r0 + tx] = tile[tx][ty + i];
}

__global__ void transpose_to(const float* __restrict__ in, float* __restrict__ out,
                             int R, int C) {
    __shared__ float tile[32][33];
    const int c0 = blockIdx.x * 32, r0 = blockIdx.y * 32;
    const int tx = threadIdx.x, ty = threadIdx.y;
    #pragma unroll
    for (int i = 0; i < 32; i += 8)
        tile[ty + i][tx] = in[(size_t)(r0 + ty + i) * C + c0 + tx];
    __syncthreads();
    #pragma unroll
    for (int i = 0; i < 32; i += 8)
        out[(size_t)(c0 + ty + i) * R + r0 + tx] = tile[tx][ty + i];
}

// ============================================================
// bf16x3 split GEMM:  C[m,n] = sum_k A[m,k]*BT[n,k] (+bias[n])
// CTA 128x128, k-chunk 32 (2 x k16 mma steps), 8 warps (2m x 4n),
// warp tile 64x32, 3 compensated bf16 MMA passes (hi*hi+hi*lo+lo*hi).
// Smem: per stage 4 arrays [128][KPB] bf16 (A_hi, A_lo, B_hi, B_lo).
// ============================================================
#define KC  32
#define KPB 40                      // bf16 elems per row (pad: banks 20g+t all distinct)
#define SST (128 * KPB)             // bf16 elems per array-tile
#define STG (4 * SST)               // bf16 elems per stage
#define GSMEM (2 * STG * 2)         // bytes = 81920

__device__ __forceinline__ void cvt_split4(const float4 v, uint32_t& h01, uint32_t& h23,
                                           uint32_t& l01, uint32_t& l23) {
    __nv_bfloat16 h0 = __float2bfloat16(v.x);
    __nv_bfloat16 h1 = __float2bfloat16(v.y);
    __nv_bfloat16 h2 = __float2bfloat16(v.z);
    __nv_bfloat16 h3 = __float2bfloat16(v.w);
    __nv_bfloat16 l0 = __float2bfloat16(v.x - __bfloat162float(h0));
    __nv_bfloat16 l1 = __float2bfloat16(v.y - __bfloat162float(h1));
    __nv_bfloat16 l2 = __float2bfloat16(v.z - __bfloat162float(h2));
    __nv_bfloat16 l3 = __float2bfloat16(v.w - __bfloat162float(h3));
    __nv_bfloat162 H01 = {h0, h1}, H23 = {h2, h3}, L01 = {l0, l1}, L23 = {l2, l3};
    h01 = *(uint32_t*)&H01; h23 = *(uint32_t*)&H23;
    l01 = *(uint32_t*)&L01; l23 = *(uint32_t*)&L23;
}

#define MMA_BF16(acc, a, b) \
    asm volatile( \
        "mma.sync.aligned.m16n8k16.row.col.f32.bf16.bf16.f32 " \
        "{%0,%1,%2,%3}, {%4,%5,%6,%7}, {%8,%9}, {%0,%1,%2,%3};" \
        : "+f"((acc)[0]), "+f"((acc)[1]), "+f"((acc)[2]), "+f"((acc)[3]) \
        : "r"((a)[0]), "r"((a)[1]), "r"((a)[2]), "r"((a)[3]), \
          "r"((b)[0]), "r"((b)[1]))

__global__ void __launch_bounds__(256) gemm_bf16x3(
    const float* __restrict__ A, const float* __restrict__ BT,
    const float* __restrict__ bias, float* __restrict__ Cout,
    int N, int K, size_t a_bstride, size_t c_bstride)
{
    extern __shared__ __align__(16) __nv_bfloat16 smem[];

    const int tid = threadIdx.x;
    const int warp = tid >> 5, lane = tid & 31;
    const int g = lane >> 2, t = lane & 3;
    const int warpM = (warp >> 2) * 64;     // 0 or 64
    const int warpN = (warp & 3) * 32;      // 0,32,64,96
    const int m0 = blockIdx.x * 128, n0 = blockIdx.y * 128;
    const float* Ab = A + blockIdx.z * a_bstride;
    float* Cb = Cout + blockIdx.z * c_bstride;

    const int lrow0 = tid >> 3;             // 0..31, rows +32 per j
    const int lkq   = (tid & 7) << 2;       // 0,4,...,28

    float acc[4][4][4];
    #pragma unroll
    for (int a = 0; a < 4; a++)
        #pragma unroll
        for (int b = 0; b < 4; b++)
            #pragma unroll
            for (int c = 0; c < 4; c++) acc[a][b][c] = 0.f;

    const int ntiles = K / KC;
    float4 pa[4], pb[4];

    // prologue: load tile 0
    #pragma unroll
    for (int j = 0; j < 4; j++) {
        const int row = lrow0 + j * 32;
        pa[j] = __ldg((const float4*)(Ab + (size_t)(m0 + row) * K + lkq));
        pb[j] = __ldg((const float4*)(BT + (size_t)(n0 + row) * K + lkq));
    }
    {
        __nv_bfloat16* st = smem;           // stage 0
        #pragma unroll
        for (int j = 0; j < 4; j++) {
            const int row = lrow0 + j * 32;
            const int off = row * KPB + lkq;
            uint32_t h01, h23, l01, l23;
            cvt_split4(pa[j], h01, h23, l01, l23);
            *(uint2*)(st + off)             = make_uint2(h01, h23);   // A_hi
            *(uint2*)(st + SST + off)       = make_uint2(l01, l23);   // A_lo
            cvt_split4(pb[j], h01, h23, l01, l23);
            *(uint2*)(st + 2 * SST + off)   = make_uint2(h01, h23);   // B_hi
            *(uint2*)(st + 3 * SST + off)   = make_uint2(l01, l23);   // B_lo
        }
    }
    __syncthreads();

    int cur = 0;
    for (int i = 0; i < ntiles; i++) {
        if (i + 1 < ntiles) {
            const int k0 = (i + 1) * KC;
            #pragma unroll
            for (int j = 0; j < 4; j++) {
                const int row = lrow0 + j * 32;
                pa[j] = __ldg((const float4*)(Ab + (size_t)(m0 + row) * K + k0 + lkq));
                pb[j] = __ldg((const float4*)(BT + (size_t)(n0 + row) * K + k0 + lkq));
            }
        }

        const __nv_bfloat16* Ah = smem + cur * STG;
        const __nv_bfloat16* Al = Ah + SST;
        const __nv_bfloat16* Bh = Ah + 2 * SST;
        const __nv_bfloat16* Bl = Ah + 3 * SST;

        #pragma unroll
        for (int kk = 0; kk < 2; kk++) {
            const int kb = kk * 16 + 2 * t;
            uint32_t ah[4][4], al[4][4], bh[4][2], bl[4][2];
            #pragma unroll
            for (int mt = 0; mt < 4; mt++) {
                const int mr = warpM + mt * 16 + g;
                ah[mt][0] = *(const uint32_t*)(Ah + (mr    ) * KPB + kb);
                ah[mt][1] = *(const uint32_t*)(Ah + (mr + 8) * KPB + kb);
                ah[mt][2] = *(const uint32_t*)(Ah + (mr    ) * KPB + kb + 8);
                ah[mt][3] = *(const uint32_t*)(Ah + (mr + 8) * KPB + kb + 8);
                al[mt][0] = *(const uint32_t*)(Al + (mr    ) * KPB + kb);
                al[mt][1] = *(const uint32_t*)(Al + (mr + 8) * KPB + kb);
                al[mt][2] = *(const uint32_t*)(Al + (mr    ) * KPB + kb + 8);
                al[mt][3] = *(const uint32_t*)(Al + (mr + 8) * KPB + kb + 8);
            }
            #pragma unroll
            for (int nt = 0; nt < 4; nt++) {
                const int nr = warpN + nt * 8 + g;
                bh[nt][0] = *(const uint32_t*)(Bh + nr * KPB + kb);
                bh[nt][1] = *(const uint32_t*)(Bh + nr * KPB + kb + 8);
                bl[nt][0] = *(const uint32_t*)(Bl + nr * KPB + kb);
                bl[nt][1] = *(const uint32_t*)(Bl + nr * KPB + kb + 8);
            }
            #pragma unroll
            for (int mt = 0; mt < 4; mt++)
                #pragma unroll
                for (int nt = 0; nt < 4; nt++) {
                    MMA_BF16(acc[mt][nt], ah[mt], bh[nt]);   // hi*hi
                    MMA_BF16(acc[mt][nt], ah[mt], bl[nt]);   // hi*lo
                    MMA_BF16(acc[mt][nt], al[mt], bh[nt]);   // lo*hi
                }
        }

        if (i + 1 < ntiles) {
            __nv_bfloat16* st = smem + (cur ^ 1) * STG;
            #pragma unroll
            for (int j = 0; j < 4; j++) {
                const int row = lrow0 + j * 32;
                const int off = row * KPB + lkq;
                uint32_t h01, h23, l01, l23;
                cvt_split4(pa[j], h01, h23, l01, l23);
                *(uint2*)(st + off)           = make_uint2(h01, h23);
                *(uint2*)(st + SST + off)     = make_uint2(l01, l23);
                cvt_split4(pb[j], h01, h23, l01, l23);
                *(uint2*)(st + 2 * SST + off) = make_uint2(h01, h23);
                *(uint2*)(st + 3 * SST + off) = make_uint2(l01, l23);
            }
        }
        __syncthreads();
        cur ^= 1;
    }

    // epilogue
    #pragma unroll
    for (int mt = 0; mt < 4; mt++) {
        const int r0 = m0 + warpM + mt * 16 + g;
        #pragma unroll
        for (int nt = 0; nt < 4; nt++) {
            const int cc = n0 + warpN + nt * 8 + 2 * t;
            float b0 = bias ? bias[cc] : 0.f;
            float b1 = bias ? bias[cc + 1] : 0.f;
            float2 o0 = make_float2(acc[mt][nt][0] + b0, acc[mt][nt][1] + b1);
            float2 o1 = make_float2(acc[mt][nt][2] + b0, acc[mt][nt][3] + b1);
            *(float2*)(Cb + (size_t)r0 * N + cc)       = o0;
            *(float2*)(Cb + (size_t)(r0 + 8) * N + cc) = o1;
        }
    }
}

// ============================================================
// Softmax + bilinear gather
// ============================================================
__global__ void sample_kernel(const float* __restrict__ ref_xy)
{
    const int bt = blockIdx.x;
    const int b  = bt >> 11;
    const int h  = threadIdx.x >> 5;
    const int lane = threadIdx.x & 31;

    const float* vb = g_v + (size_t)b * HW_ * D_;
    const float rx = ref_xy[(size_t)bt * 2 + 0];
    const float ry = ref_xy[(size_t)bt * 2 + 1];

    const float* pr = g_proj + (size_t)bt * NQ_;

    float wv = -INFINITY, ox = 0.f, oy = 0.f;
    if (lane < P_) {
        wv = pr[256 + h * P_ + lane];
        ox = pr[(h * P_ + lane) * 2 + 0];
        oy = pr[(h * P_ + lane) * 2 + 1];
    }
    float m = wv;
    #pragma unroll
    for (int o = 8; o >= 1; o >>= 1) m = fmaxf(m, __shfl_xor_sync(0xffffffffu, m, o));
    float e = (lane < P_) ? __expf(wv - m) : 0.f;
    float s = e;
    #pragma unroll
    for (int o = 8; o >= 1; o >>= 1) s += __shfl_xor_sync(0xffffffffu, s, o);
    const float aw = (lane < P_) ? (e / s) : 0.f;

    const float ix = (rx + RADIUS_ * ox) * (float)(WF_ - 1);
    const float iy = (ry + RADIUS_ * oy) * (float)(HF_ - 1);
    const float fx0 = floorf(ix), fy0 = floorf(iy);
    const int   x0 = (int)fx0,   y0 = (int)fy0;
    const float fx = ix - fx0,   fy = iy - fy0;

    int   idxc[4];
    float wc[4];
    {
        const int x1 = x0 + 1, y1 = y0 + 1;
        const int xs[4] = {x0, x1, x0, x1};
        const int ys[4] = {y0, y0, y1, y1};
        const float ww[4] = {(1.f - fx) * (1.f - fy), fx * (1.f - fy),
                             (1.f - fx) * fy,         fx * fy};
        #pragma unroll
        for (int c = 0; c < 4; c++) {
            const bool valid = (xs[c] >= 0) & (xs[c] < WF_) & (ys[c] >= 0) & (ys[c] < HF_);
            const int xc = min(max(xs[c], 0), WF_ - 1);
            const int yc = min(max(ys[c], 0), HF_ - 1);
            idxc[c] = yc * WF_ + xc;
            wc[c]   = valid ? (ww[c] * aw) : 0.f;
        }
    }

    float acc0 = 0.f, acc1 = 0.f;
    const int hbase = h * DH_;
    #pragma unroll 4
    for (int p = 0; p < P_; p++) {
        #pragma unroll
        for (int c = 0; c < 4; c++) {
            const int   idx = __shfl_sync(0xffffffffu, idxc[c], p);
            const float w   = __shfl_sync(0xffffffffu, wc[c],   p);
            if (w != 0.f) {
                const float* vp = vb + (size_t)idx * D_ + hbase;
                acc0 += w * vp[lane];
                acc1 += w * vp[lane + 32];
            }
        }
    }
    float* cp = g_ctx + (size_t)bt * D_ + hbase;
    cp[lane]      = acc0;
    cp[lane + 32] = acc1;
}

// ============================================================
extern "C" void kernel_launch(void* const* d_in, const int* in_sizes, int n_in,
                              void* d_out, int out_size)
{
    const float* q      = (const float*)d_in[0];
    const float* fmap   = (const float*)d_in[1];
    const float* ref_xy = (const float*)d_in[2];
    const float* Wv     = (const float*)d_in[3];
    const float* W_off  = (const float*)d_in[4];
    const float* b_off  = (const float*)d_in[5];
    const float* W_w    = (const float*)d_in[6];
    const float* b_w    = (const float*)d_in[7];
    const float* W_out  = (const float*)d_in[8];
    const float* b_out  = (const float*)d_in[9];
    float* out = (float*)d_out;

    float *v, *proj, *ctx, *fmapT, *WvT, *WoutT, *WqT, *bq;
    cudaGetSymbolAddress((void**)&v,     g_v);
    cudaGetSymbolAddress((void**)&proj,  g_proj);
    cudaGetSymbolAddress((void**)&ctx,   g_ctx);
    cudaGetSymbolAddress((void**)&fmapT, g_fmapT);
    cudaGetSymbolAddress((void**)&WvT,   g_WvT);
    cudaGetSymbolAddress((void**)&WoutT, g_WoutT);
    cudaGetSymbolAddress((void**)&WqT,   g_WqT);
    cudaGetSymbolAddress((void**)&bq,    g_bq);

    cudaFuncSetAttribute(gemm_bf16x3, cudaFuncAttributeMaxDynamicSharedMemorySize, GSMEM);

    // prep: transposes + bias concat
    transpose_kernel<<<dim3(HW_ / 32, C_ / 32, B_), dim3(32, 8)>>>(fmap, fmapT, C_, HW_);
    transpose_to<<<dim3(C_ / 32, D_ / 32), dim3(32, 8)>>>(Wv, WvT, C_, D_);
    transpose_to<<<dim3(D_ / 32, D_ / 32), dim3(32, 8)>>>(W_out, WoutT, D_, D_);
    transpose_to<<<dim3((H_*P_*2) / 32, D_ / 32), dim3(32, 8)>>>(W_off, WqT, D_, H_*P_*2);
    transpose_to<<<dim3((H_*P_) / 32, D_ / 32), dim3(32, 8)>>>(W_w, WqT + 256 * D_, D_, H_*P_);
    cudaMemcpyAsync(bq,       b_off, 256 * sizeof(float), cudaMemcpyDeviceToDevice);
    cudaMemcpyAsync(bq + 256, b_w,   128 * sizeof(float), cudaMemcpyDeviceToDevice);

    // K1: v[b] = fmapT[b] @ Wv   (M=4096/batch, N=512, K=512)
    gemm_bf16x3<<<dim3(HW_ / 128, D_ / 128, B_), 256, GSMEM>>>(
        fmapT, WvT, (const float*)0, v, D_, C_, (size_t)HW_ * C_, (size_t)HW_ * D_);

    // K2: proj = q @ [W_off|W_w] + bias   (M=8192, N=384, K=512)
    gemm_bf16x3<<<dim3(M_BT / 128, NQ_ / 128, 1), 256, GSMEM>>>(
        q, WqT, bq, proj, NQ_, D_, 0, 0);

    // K3: softmax + bilinear gather -> ctx
    sample_kernel<<<M_BT, H_ * 32>>>(ref_xy);

    // K4: out = ctx @ W_out + b_out   (M=8192, N=512, K=512)
    gemm_bf16x3<<<dim3(M_BT / 128, D_ / 128, 1), 256, GSMEM>>>(
        ctx, WoutT, b_out, out, D_, D_, 0, 0);
}

// round 6
// speedup vs baseline: 1.7958x; 1.0568x over previous
#include <cuda_runtime.h>
#include <cuda_bf16.h>
#include <math.h>
#include <stdint.h>

#define B_  4
#define T_  2048
#define D_  512
#define H_  8
#define P_  16
#define DH_ 64
#define C_  512
#define HF_ 64
#define WF_ 64
#define HW_ (HF_*WF_)
#define RADIUS_ 0.08f
#define M_BT (B_*T_)          // 8192
#define NQ_ (H_*P_*2 + H_*P_) // 384

// ---- scratch ----
__device__ float g_v    [(size_t)B_*HW_*D_];
__device__ float g_proj [(size_t)M_BT*NQ_];
__device__ float g_ctx  [(size_t)M_BT*D_];
__device__ float g_fmapT[(size_t)B_*HW_*C_];
__device__ float g_WvT  [(size_t)D_*C_];
__device__ float g_WoutT[(size_t)D_*D_];
__device__ float g_WqT  [(size_t)NQ_*D_];
__device__ float g_bq   [NQ_];

// ============================================================
// fmap transpose: in [B][C][HW] -> out [B][HW][C]
// ============================================================
__global__ void transpose_kernel(const float* __restrict__ in, float* __restrict__ out,
                                 int R, int C) {
    __shared__ float tile[32][33];
    const size_t bo = (size_t)blockIdx.z * R * C;
    const int c0 = blockIdx.x * 32, r0 = blockIdx.y * 32;
    const int tx = threadIdx.x, ty = threadIdx.y;
    #pragma unroll
    for (int i = 0; i < 32; i += 8)
        tile[ty + i][tx] = in[bo + (size_t)(r0 + ty + i) * C + c0 + tx];
    __syncthreads();
    #pragma unroll
    for (int i = 0; i < 32; i += 8)
        out[bo + (size_t)(c0 + ty + i) * R + r0 + tx] = tile[tx][ty + i];
}

// ============================================================
// All weight transposes + bias concat in ONE launch.
// z=0: Wv[512,512]->WvT ; z=1: W_out->WoutT ;
// z=2: W_off[512,256]->WqT[0:256] ; z=3: W_w[512,128]->WqT[256:384] (+bias)
// ============================================================
__global__ void prep_weights(const float* __restrict__ Wv,  const float* __restrict__ Wout,
                             const float* __restrict__ Woff, const float* __restrict__ Ww,
                             const float* __restrict__ boff, const float* __restrict__ bw)
{
    __shared__ float tile[32][33];
    const int z = blockIdx.z;
    const float* in; float* out; int Ccols;
    if      (z == 0) { in = Wv;   out = g_WvT;            Ccols = 512; }
    else if (z == 1) { in = Wout; out = g_WoutT;          Ccols = 512; }
    else if (z == 2) { in = Woff; out = g_WqT;            Ccols = 256; }
    else             { in = Ww;   out = g_WqT + 256 * D_; Ccols = 128; }
    const int R = 512;
    const int tx = threadIdx.x, ty = threadIdx.y;

    if (z == 3 && blockIdx.x == 0 && blockIdx.y == 0) {
        const int idx0 = ty * 32 + tx;
        for (int i = idx0; i < NQ_; i += 256)
            g_bq[i] = (i < 256) ? boff[i] : bw[i - 256];
    }

    const int c0 = blockIdx.x * 32, r0 = blockIdx.y * 32;
    if (c0 >= Ccols) return;
    #pragma unroll
    for (int i = 0; i < 32; i += 8)
        tile[ty + i][tx] = in[(size_t)(r0 + ty + i) * Ccols + c0 + tx];
    __syncthreads();
    #pragma unroll
    for (int i = 0; i < 32; i += 8)
        out[(size_t)(c0 + ty + i) * R + r0 + tx] = tile[tx][ty + i];
}

// ============================================================
// bf16x3 split GEMM with ldmatrix fragment loads.
// C[m,n] = sum_k A[m,k]*BT[n,k] (+bias[n]); CTA 128x128, k-chunk 32,
// 8 warps (2m x 4n), warp tile 64x32.
// ============================================================
#define KC  32
#define KPB 40
#define SST (128 * KPB)
#define STG (4 * SST)
#define GSMEM (2 * STG * 2)

__device__ __forceinline__ void cvt_split4(const float4 v, uint32_t& h01, uint32_t& h23,
                                           uint32_t& l01, uint32_t& l23) {
    __nv_bfloat16 h0 = __float2bfloat16(v.x);
    __nv_bfloat16 h1 = __float2bfloat16(v.y);
    __nv_bfloat16 h2 = __float2bfloat16(v.z);
    __nv_bfloat16 h3 = __float2bfloat16(v.w);
    __nv_bfloat16 l0 = __float2bfloat16(v.x - __bfloat162float(h0));
    __nv_bfloat16 l1 = __float2bfloat16(v.y - __bfloat162float(h1));
    __nv_bfloat16 l2 = __float2bfloat16(v.z - __bfloat162float(h2));
    __nv_bfloat16 l3 = __float2bfloat16(v.w - __bfloat162float(h3));
    __nv_bfloat162 H01 = {h0, h1}, H23 = {h2, h3}, L01 = {l0, l1}, L23 = {l2, l3};
    h01 = *(uint32_t*)&H01; h23 = *(uint32_t*)&H23;
    l01 = *(uint32_t*)&L01; l23 = *(uint32_t*)&L23;
}

#define MMA_BF16(acc, a, b) \
    asm volatile( \
        "mma.sync.aligned.m16n8k16.row.col.f32.bf16.bf16.f32 " \
        "{%0,%1,%2,%3}, {%4,%5,%6,%7}, {%8,%9}, {%0,%1,%2,%3};" \
        : "+f"((acc)[0]), "+f"((acc)[1]), "+f"((acc)[2]), "+f"((acc)[3]) \
        : "r"((a)[0]), "r"((a)[1]), "r"((a)[2]), "r"((a)[3]), \
          "r"((b)[0]), "r"((b)[1]))

#define LDM_X4(r, addr) \
    asm volatile("ldmatrix.sync.aligned.m8n8.x4.shared.b16 {%0,%1,%2,%3}, [%4];" \
        : "=r"((r)[0]), "=r"((r)[1]), "=r"((r)[2]), "=r"((r)[3]) : "r"(addr))
#define LDM_X2(r, addr) \
    asm volatile("ldmatrix.sync.aligned.m8n8.x2.shared.b16 {%0,%1}, [%2];" \
        : "=r"((r)[0]), "=r"((r)[1]) : "r"(addr))

__global__ void __launch_bounds__(256) gemm_bf16x3(
    const float* __restrict__ A, const float* __restrict__ BT,
    const float* __restrict__ bias, float* __restrict__ Cout,
    int N, int K, size_t a_bstride, size_t c_bstride)
{
    extern __shared__ __align__(16) __nv_bfloat16 smem[];

    const int tid = threadIdx.x;
    const int warp = tid >> 5, lane = tid & 31;
    const int g = lane >> 2, t = lane & 3;
    const int warpM = (warp >> 2) * 64;
    const int warpN = (warp & 3) * 32;
    const int m0 = blockIdx.x * 128, n0 = blockIdx.y * 128;
    const float* Ab = A + blockIdx.z * a_bstride;
    float* Cb = Cout + blockIdx.z * c_bstride;

    const int lrow0 = tid >> 3;
    const int lkq   = (tid & 7) << 2;

    // ldmatrix per-lane offsets (in bf16 elements)
    const int aRow = (lane & 7) + ((lane >> 3) & 1) * 8;   // 0..15
    const int aK8  = (lane >> 4) * 8;                      // 0 or 8
    const int bRow = lane & 7;
    const int bK8  = ((lane >> 3) & 1) * 8;

    const uint32_t smem_base = (uint32_t)__cvta_generic_to_shared(smem);
    // byte offset helpers
    const uint32_t aLaneOff = (uint32_t)((warpM + aRow) * KPB + aK8) * 2;
    const uint32_t bLaneOff = (uint32_t)((warpN + bRow) * KPB + bK8) * 2;

    float acc[4][4][4];
    #pragma unroll
    for (int a = 0; a < 4; a++)
        #pragma unroll
        for (int b = 0; b < 4; b++)
            #pragma unroll
            for (int c = 0; c < 4; c++) acc[a][b][c] = 0.f;

    const int ntiles = K / KC;
    float4 pa[4], pb[4];

    #pragma unroll
    for (int j = 0; j < 4; j++) {
        const int row = lrow0 + j * 32;
        pa[j] = __ldg((const float4*)(Ab + (size_t)(m0 + row) * K + lkq));
        pb[j] = __ldg((const float4*)(BT + (size_t)(n0 + row) * K + lkq));
    }
    {
        __nv_bfloat16* st = smem;
        #pragma unroll
        for (int j = 0; j < 4; j++) {
            const int row = lrow0 + j * 32;
            const int off = row * KPB + lkq;
            uint32_t h01, h23, l01, l23;
            cvt_split4(pa[j], h01, h23, l01, l23);
            *(uint2*)(st + off)           = make_uint2(h01, h23);
            *(uint2*)(st + SST + off)     = make_uint2(l01, l23);
            cvt_split4(pb[j], h01, h23, l01, l23);
            *(uint2*)(st + 2 * SST + off) = make_uint2(h01, h23);
            *(uint2*)(st + 3 * SST + off) = make_uint2(l01, l23);
        }
    }
    __syncthreads();

    int cur = 0;
    for (int i = 0; i < ntiles; i++) {
        if (i + 1 < ntiles) {
            const int k0 = (i + 1) * KC;
            #pragma unroll
            for (int j = 0; j < 4; j++) {
                const int row = lrow0 + j * 32;
                pa[j] = __ldg((const float4*)(Ab + (size_t)(m0 + row) * K + k0 + lkq));
                pb[j] = __ldg((const float4*)(BT + (size_t)(n0 + row) * K + k0 + lkq));
            }
        }

        const uint32_t stg = smem_base + (uint32_t)(cur * STG) * 2;
        const uint32_t AhB = stg + aLaneOff;
        const uint32_t AlB = AhB + SST * 2;
        const uint32_t BhB = stg + 2 * (SST * 2) + bLaneOff;
        const uint32_t BlB = BhB + SST * 2;

        #pragma unroll
        for (int kk = 0; kk < 2; kk++) {
            const uint32_t kOff = (uint32_t)(kk * 16) * 2;
            uint32_t ah[4][4], al[4][4], bh[4][2], bl[4][2];
            #pragma unroll
            for (int mt = 0; mt < 4; mt++) {
                const uint32_t mo = (uint32_t)(mt * 16 * KPB) * 2 + kOff;
                LDM_X4(ah[mt], AhB + mo);
                LDM_X4(al[mt], AlB + mo);
            }
            #pragma unroll
            for (int nt = 0; nt < 4; nt++) {
                const uint32_t no = (uint32_t)(nt * 8 * KPB) * 2 + kOff;
                LDM_X2(bh[nt], BhB + no);
                LDM_X2(bl[nt], BlB + no);
            }
            #pragma unroll
            for (int mt = 0; mt < 4; mt++)
                #pragma unroll
                for (int nt = 0; nt < 4; nt++) {
                    MMA_BF16(acc[mt][nt], ah[mt], bh[nt]);
                    MMA_BF16(acc[mt][nt], ah[mt], bl[nt]);
                    MMA_BF16(acc[mt][nt], al[mt], bh[nt]);
                }
        }

        if (i + 1 < ntiles) {
            __nv_bfloat16* st = smem + (cur ^ 1) * STG;
            #pragma unroll
            for (int j = 0; j < 4; j++) {
                const int row = lrow0 + j * 32;
                const int off = row * KPB + lkq;
                uint32_t h01, h23, l01, l23;
                cvt_split4(pa[j], h01, h23, l01, l23);
                *(uint2*)(st + off)           = make_uint2(h01, h23);
                *(uint2*)(st + SST + off)     = make_uint2(l01, l23);
                cvt_split4(pb[j], h01, h23, l01, l23);
                *(uint2*)(st + 2 * SST + off) = make_uint2(h01, h23);
                *(uint2*)(st + 3 * SST + off) = make_uint2(l01, l23);
            }
        }
        __syncthreads();
        cur ^= 1;
    }

    #pragma unroll
    for (int mt = 0; mt < 4; mt++) {
        const int r0 = m0 + warpM + mt * 16 + g;
        #pragma unroll
        for (int nt = 0; nt < 4; nt++) {
            const int cc = n0 + warpN + nt * 8 + 2 * t;
            float b0 = bias ? bias[cc] : 0.f;
            float b1 = bias ? bias[cc + 1] : 0.f;
            float2 o0 = make_float2(acc[mt][nt][0] + b0, acc[mt][nt][1] + b1);
            float2 o1 = make_float2(acc[mt][nt][2] + b0, acc[mt][nt][3] + b1);
            *(float2*)(Cb + (size_t)r0 * N + cc)       = o0;
            *(float2*)(Cb + (size_t)(r0 + 8) * N + cc) = o1;
        }
    }
}

// ============================================================
// Softmax + bilinear gather
// ============================================================
__global__ void sample_kernel(const float* __restrict__ ref_xy)
{
    const int bt = blockIdx.x;
    const int b  = bt >> 11;
    const int h  = threadIdx.x >> 5;
    const int lane = threadIdx.x & 31;

    const float* vb = g_v + (size_t)b * HW_ * D_;
    const float rx = ref_xy[(size_t)bt * 2 + 0];
    const float ry = ref_xy[(size_t)bt * 2 + 1];

    const float* pr = g_proj + (size_t)bt * NQ_;

    float wv = -INFINITY, ox = 0.f, oy = 0.f;
    if (lane < P_) {
        wv = pr[256 + h * P_ + lane];
        ox = pr[(h * P_ + lane) * 2 + 0];
        oy = pr[(h * P_ + lane) * 2 + 1];
    }
    float m = wv;
    #pragma unroll
    for (int o = 8; o >= 1; o >>= 1) m = fmaxf(m, __shfl_xor_sync(0xffffffffu, m, o));
    float e = (lane < P_) ? __expf(wv - m) : 0.f;
    float s = e;
    #pragma unroll
    for (int o = 8; o >= 1; o >>= 1) s += __shfl_xor_sync(0xffffffffu, s, o);
    const float aw = (lane < P_) ? (e / s) : 0.f;

    const float ix = (rx + RADIUS_ * ox) * (float)(WF_ - 1);
    const float iy = (ry + RADIUS_ * oy) * (float)(HF_ - 1);
    const float fx0 = floorf(ix), fy0 = floorf(iy);
    const int   x0 = (int)fx0,   y0 = (int)fy0;
    const float fx = ix - fx0,   fy = iy - fy0;

    int   idxc[4];
    float wc[4];
    {
        const int x1 = x0 + 1, y1 = y0 + 1;
        const int xs[4] = {x0, x1, x0, x1};
        const int ys[4] = {y0, y0, y1, y1};
        const float ww[4] = {(1.f - fx) * (1.f - fy), fx * (1.f - fy),
                             (1.f - fx) * fy,         fx * fy};
        #pragma unroll
        for (int c = 0; c < 4; c++) {
            const bool valid = (xs[c] >= 0) & (xs[c] < WF_) & (ys[c] >= 0) & (ys[c] < HF_);
            const int xc = min(max(xs[c], 0), WF_ - 1);
            const int yc = min(max(ys[c], 0), HF_ - 1);
            idxc[c] = yc * WF_ + xc;
            wc[c]   = valid ? (ww[c] * aw) : 0.f;
        }
    }

    float acc0 = 0.f, acc1 = 0.f;
    const int hbase = h * DH_;
    #pragma unroll 4
    for (int p = 0; p < P_; p++) {
        #pragma unroll
        for (int c = 0; c < 4; c++) {
            const int   idx = __shfl_sync(0xffffffffu, idxc[c], p);
            const float w   = __shfl_sync(0xffffffffu, wc[c],   p);
            if (w != 0.f) {
                const float* vp = vb + (size_t)idx * D_ + hbase;
                acc0 += w * vp[lane];
                acc1 += w * vp[lane + 32];
            }
        }
    }
    float* cp = g_ctx + (size_t)bt * D_ + hbase;
    cp[lane]      = acc0;
    cp[lane + 32] = acc1;
}

// ============================================================
extern "C" void kernel_launch(void* const* d_in, const int* in_sizes, int n_in,
                              void* d_out, int out_size)
{
    const float* q      = (const float*)d_in[0];
    const float* fmap   = (const float*)d_in[1];
    const float* ref_xy = (const float*)d_in[2];
    const float* Wv     = (const float*)d_in[3];
    const float* W_off  = (const float*)d_in[4];
    const float* b_off  = (const float*)d_in[5];
    const float* W_w    = (const float*)d_in[6];
    const float* b_w    = (const float*)d_in[7];
    const float* W_out  = (const float*)d_in[8];
    const float* b_out  = (const float*)d_in[9];
    float* out = (float*)d_out;

    float *v, *proj, *ctx, *fmapT, *WvT, *WoutT, *WqT, *bq;
    cudaGetSymbolAddress((void**)&v,     g_v);
    cudaGetSymbolAddress((void**)&proj,  g_proj);
    cudaGetSymbolAddress((void**)&ctx,   g_ctx);
    cudaGetSymbolAddress((void**)&fmapT, g_fmapT);
    cudaGetSymbolAddress((void**)&WvT,   g_WvT);
    cudaGetSymbolAddress((void**)&WoutT, g_WoutT);
    cudaGetSymbolAddress((void**)&WqT,   g_WqT);
    cudaGetSymbolAddress((void**)&bq,    g_bq);

    cudaFuncSetAttribute(gemm_bf16x3, cudaFuncAttributeMaxDynamicSharedMemorySize, GSMEM);

    // L1: fmap [B,C,HW] -> fmapT [B,HW,C]
    transpose_kernel<<<dim3(HW_ / 32, C_ / 32, B_), dim3(32, 8)>>>(fmap, fmapT, C_, HW_);
    // L2: all weight transposes + bias concat
    prep_weights<<<dim3(16, 16, 4), dim3(32, 8)>>>(Wv, W_out, W_off, W_w, b_off, b_w);

    // L3: v[b] = fmapT[b] @ Wv
    gemm_bf16x3<<<dim3(HW_ / 128, D_ / 128, B_), 256, GSMEM>>>(
        fmapT, WvT, (const float*)0, v, D_, C_, (size_t)HW_ * C_, (size_t)HW_ * D_);

    // L4: proj = q @ [W_off|W_w] + bias
    gemm_bf16x3<<<dim3(M_BT / 128, NQ_ / 128, 1), 256, GSMEM>>>(
        q, WqT, bq, proj, NQ_, D_, 0, 0);

    // L5: softmax + bilinear gather -> ctx
    sample_kernel<<<M_BT, H_ * 32>>>(ref_xy);

    // L6: out = ctx @ W_out + b_out   (<- ncu -s 5 -c 1 captures this)
    gemm_bf16x3<<<dim3(M_BT / 128, D_ / 128, 1), 256, GSMEM>>>(
        ctx, WoutT, b_out, out, D_, D_, 0, 0);
}

// round 8
// speedup vs baseline: 1.8038x; 1.0045x over previous
#include <cuda_runtime.h>
#include <cuda_bf16.h>
#include <math.h>
#include <stdint.h>

#define B_  4
#define T_  2048
#define D_  512
#define H_  8
#define P_  16
#define DH_ 64
#define C_  512
#define HF_ 64
#define WF_ 64
#define HW_ (HF_*WF_)
#define RADIUS_ 0.08f
#define M_BT (B_*T_)
#define NQ_ (H_*P_*2 + H_*P_)

// ---- scratch ----
__device__ float g_v    [(size_t)B_*HW_*D_];
__device__ float g_proj [(size_t)M_BT*NQ_];
__device__ float g_ctx  [(size_t)M_BT*D_];
__device__ float g_fmapT[(size_t)B_*HW_*C_];
__device__ float g_WvT  [(size_t)D_*C_];
__device__ float g_WoutT[(size_t)D_*D_];
__device__ float g_WqT  [(size_t)NQ_*D_];
__device__ float g_bq   [NQ_];

// ============================================================
// fmap transpose: [B][C][HW] -> [B][HW][C]
// ============================================================
__global__ void transpose_kernel(const float* __restrict__ in, float* __restrict__ out,
                                 int R, int C) {
    __shared__ float tile[32][33];
    const size_t bo = (size_t)blockIdx.z * R * C;
    const int c0 = blockIdx.x * 32, r0 = blockIdx.y * 32;
    const int tx = threadIdx.x, ty = threadIdx.y;
    #pragma unroll
    for (int i = 0; i < 32; i += 8)
        tile[ty + i][tx] = in[bo + (size_t)(r0 + ty + i) * C + c0 + tx];
    __syncthreads();
    #pragma unroll
    for (int i = 0; i < 32; i += 8)
        out[bo + (size_t)(c0 + ty + i) * R + r0 + tx] = tile[tx][ty + i];
}

// ============================================================
// Weight transposes + bias concat (one launch)
// ============================================================
__global__ void prep_weights(const float* __restrict__ Wv,  const float* __restrict__ Wout,
                             const float* __restrict__ Woff, const float* __restrict__ Ww,
                             const float* __restrict__ boff, const float* __restrict__ bw)
{
    __shared__ float tile[32][33];
    const int z = blockIdx.z;
    const float* in; float* out; int Ccols;
    if      (z == 0) { in = Wv;   out = g_WvT;            Ccols = 512; }
    else if (z == 1) { in = Wout; out = g_WoutT;          Ccols = 512; }
    else if (z == 2) { in = Woff; out = g_WqT;            Ccols = 256; }
    else             { in = Ww;   out = g_WqT + 256 * D_; Ccols = 128; }
    const int R = 512;
    const int tx = threadIdx.x, ty = threadIdx.y;

    if (z == 3 && blockIdx.x == 0 && blockIdx.y == 0) {
        const int idx0 = ty * 32 + tx;
        for (int i = idx0; i < NQ_; i += 256)
            g_bq[i] = (i < 256) ? boff[i] : bw[i - 256];
    }

    const int c0 = blockIdx.x * 32, r0 = blockIdx.y * 32;
    if (c0 >= Ccols) return;
    #pragma unroll
    for (int i = 0; i < 32; i += 8)
        tile[ty + i][tx] = in[(size_t)(r0 + ty + i) * Ccols + c0 + tx];
    __syncthreads();
    #pragma unroll
    for (int i = 0; i < 32; i += 8)
        out[(size_t)(c0 + ty + i) * R + r0 + tx] = tile[tx][ty + i];
}

// ============================================================
// bf16x3 split GEMM, 512 threads (16 warps, 4m x 4n), warp tile 32x32.
// C[m,n] = sum_k A[m,k]*BT[n,k] (+bias[n]); CTA 128x128, k-chunk 32.
// ============================================================
#define KC  32
#define KPB 40
#define SST (128 * KPB)
#define STG (4 * SST)
#define GSMEM (2 * STG * 2)

__device__ __forceinline__ void cvt_split4(const float4 v, uint32_t& h01, uint32_t& h23,
                                           uint32_t& l01, uint32_t& l23) {
    __nv_bfloat16 h0 = __float2bfloat16(v.x);
    __nv_bfloat16 h1 = __float2bfloat16(v.y);
    __nv_bfloat16 h2 = __float2bfloat16(v.z);
    __nv_bfloat16 h3 = __float2bfloat16(v.w);
    __nv_bfloat16 l0 = __float2bfloat16(v.x - __bfloat162float(h0));
    __nv_bfloat16 l1 = __float2bfloat16(v.y - __bfloat162float(h1));
    __nv_bfloat16 l2 = __float2bfloat16(v.z - __bfloat162float(h2));
    __nv_bfloat16 l3 = __float2bfloat16(v.w - __bfloat162float(h3));
    __nv_bfloat162 H01 = {h0, h1}, H23 = {h2, h3}, L01 = {l0, l1}, L23 = {l2, l3};
    h01 = *(uint32_t*)&H01; h23 = *(uint32_t*)&H23;
    l01 = *(uint32_t*)&L01; l23 = *(uint32_t*)&L23;
}

#define MMA_BF16(acc, a, b) \
    asm volatile( \
        "mma.sync.aligned.m16n8k16.row.col.f32.bf16.bf16.f32 " \
        "{%0,%1,%2,%3}, {%4,%5,%6,%7}, {%8,%9}, {%0,%1,%2,%3};" \
        : "+f"((acc)[0]), "+f"((acc)[1]), "+f"((acc)[2]), "+f"((acc)[3]) \
        : "r"((a)[0]), "r"((a)[1]), "r"((a)[2]), "r"((a)[3]), \
          "r"((b)[0]), "r"((b)[1]))

#define LDM_X4(r, addr) \
    asm volatile("ldmatrix.sync.aligned.m8n8.x4.shared.b16 {%0,%1,%2,%3}, [%4];" \
        : "=r"((r)[0]), "=r"((r)[1]), "=r"((r)[2]), "=r"((r)[3]) : "r"(addr))
#define LDM_X2(r, addr) \
    asm volatile("ldmatrix.sync.aligned.m8n8.x2.shared.b16 {%0,%1}, [%2];" \
        : "=r"((r)[0]), "=r"((r)[1]) : "r"(addr))

__global__ void __launch_bounds__(512) gemm_bf16x3(
    const float* __restrict__ A, const float* __restrict__ BT,
    const float* __restrict__ bias, float* __restrict__ Cout,
    int N, int K, size_t a_bstride, size_t c_bstride)
{
    extern __shared__ __align__(16) __nv_bfloat16 smem[];

    const int tid = threadIdx.x;
    const int warp = tid >> 5, lane = tid & 31;
    const int g = lane >> 2, t = lane & 3;
    const int warpM = (warp >> 2) * 32;     // 0,32,64,96
    const int warpN = (warp & 3) * 32;      // 0,32,64,96
    const int m0 = blockIdx.x * 128, n0 = blockIdx.y * 128;
    const float* Ab = A + blockIdx.z * a_bstride;
    float* Cb = Cout + blockIdx.z * c_bstride;

    const int lrow0 = tid >> 3;             // 0..63, +64 per j
    const int lkq   = (tid & 7) << 2;

    const int aRow = (lane & 7) + ((lane >> 3) & 1) * 8;
    const int aK8  = (lane >> 4) * 8;
    const int bRow = lane & 7;
    const int bK8  = ((lane >> 3) & 1) * 8;

    const uint32_t smem_base = (uint32_t)__cvta_generic_to_shared(smem);
    const uint32_t aLaneOff = (uint32_t)((warpM + aRow) * KPB + aK8) * 2;
    const uint32_t bLaneOff = (uint32_t)((warpN + bRow) * KPB + bK8) * 2;

    float acc[2][4][4];
    #pragma unroll
    for (int a = 0; a < 2; a++)
        #pragma unroll
        for (int b = 0; b < 4; b++)
            #pragma unroll
            for (int c = 0; c < 4; c++) acc[a][b][c] = 0.f;

    const int ntiles = K / KC;
    float4 pa[2], pb[2];

    #pragma unroll
    for (int j = 0; j < 2; j++) {
        const int row = lrow0 + j * 64;
        pa[j] = __ldg((const float4*)(Ab + (size_t)(m0 + row) * K + lkq));
        pb[j] = __ldg((const float4*)(BT + (size_t)(n0 + row) * K + lkq));
    }
    {
        __nv_bfloat16* st = smem;
        #pragma unroll
        for (int j = 0; j < 2; j++) {
            const int row = lrow0 + j * 64;
            const int off = row * KPB + lkq;
            uint32_t h01, h23, l01, l23;
            cvt_split4(pa[j], h01, h23, l01, l23);
            *(uint2*)(st + off)           = make_uint2(h01, h23);
            *(uint2*)(st + SST + off)     = make_uint2(l01, l23);
            cvt_split4(pb[j], h01, h23, l01, l23);
            *(uint2*)(st + 2 * SST + off) = make_uint2(h01, h23);
            *(uint2*)(st + 3 * SST + off) = make_uint2(l01, l23);
        }
    }
    __syncthreads();

    int cur = 0;
    for (int i = 0; i < ntiles; i++) {
        if (i + 1 < ntiles) {
            const int k0 = (i + 1) * KC;
            #pragma unroll
            for (int j = 0; j < 2; j++) {
                const int row = lrow0 + j * 64;
                pa[j] = __ldg((const float4*)(Ab + (size_t)(m0 + row) * K + k0 + lkq));
                pb[j] = __ldg((const float4*)(BT + (size_t)(n0 + row) * K + k0 + lkq));
            }
        }

        const uint32_t stg = smem_base + (uint32_t)(cur * STG) * 2;
        const uint32_t AhB = stg + aLaneOff;
        const uint32_t AlB = AhB + SST * 2;
        const uint32_t BhB = stg + 2 * (SST * 2) + bLaneOff;
        const uint32_t BlB = BhB + SST * 2;

        #pragma unroll
        for (int kk = 0; kk < 2; kk++) {
            const uint32_t kOff = (uint32_t)(kk * 16) * 2;
            uint32_t ah[2][4], al[2][4], bh[4][2], bl[4][2];
            #pragma unroll
            for (int mt = 0; mt < 2; mt++) {
                const uint32_t mo = (uint32_t)(mt * 16 * KPB) * 2 + kOff;
                LDM_X4(ah[mt], AhB + mo);
                LDM_X4(al[mt], AlB + mo);
            }
            #pragma unroll
            for (int nt = 0; nt < 4; nt++) {
                const uint32_t no = (uint32_t)(nt * 8 * KPB) * 2 + kOff;
                LDM_X2(bh[nt], BhB + no);
                LDM_X2(bl[nt], BlB + no);
            }
            #pragma unroll
            for (int mt = 0; mt < 2; mt++)
                #pragma unroll
                for (int nt = 0; nt < 4; nt++) {
                    MMA_BF16(acc[mt][nt], ah[mt], bh[nt]);
                    MMA_BF16(acc[mt][nt], ah[mt], bl[nt]);
                    MMA_BF16(acc[mt][nt], al[mt], bh[nt]);
                }
        }

        if (i + 1 < ntiles) {
            __nv_bfloat16* st = smem + (cur ^ 1) * STG;
            #pragma unroll
            for (int j = 0; j < 2; j++) {
                const int row = lrow0 + j * 64;
                const int off = row * KPB + lkq;
                uint32_t h01, h23, l01, l23;
                cvt_split4(pa[j], h01, h23, l01, l23);
                *(uint2*)(st + off)           = make_uint2(h01, h23);
                *(uint2*)(st + SST + off)     = make_uint2(l01, l23);
                cvt_split4(pb[j], h01, h23, l01, l23);
                *(uint2*)(st + 2 * SST + off) = make_uint2(h01, h23);
                *(uint2*)(st + 3 * SST + off) = make_uint2(l01, l23);
            }
        }
        __syncthreads();
        cur ^= 1;
    }

    #pragma unroll
    for (int mt = 0; mt < 2; mt++) {
        const int r0 = m0 + warpM + mt * 16 + g;
        #pragma unroll
        for (int nt = 0; nt < 4; nt++) {
            const int cc = n0 + warpN + nt * 8 + 2 * t;
            float b0 = bias ? bias[cc] : 0.f;
            float b1 = bias ? bias[cc + 1] : 0.f;
            float2 o0 = make_float2(acc[mt][nt][0] + b0, acc[mt][nt][1] + b1);
            float2 o1 = make_float2(acc[mt][nt][2] + b0, acc[mt][nt][3] + b1);
            *(float2*)(Cb + (size_t)r0 * N + cc)       = o0;
            *(float2*)(Cb + (size_t)(r0 + 8) * N + cc) = o1;
        }
    }
}

// ============================================================
// Softmax + bilinear gather
// ============================================================
__global__ void sample_kernel(const float* __restrict__ ref_xy)
{
    const int bt = blockIdx.x;
    const int b  = bt >> 11;
    const int h  = threadIdx.x >> 5;
    const int lane = threadIdx.x & 31;

    const float* vb = g_v + (size_t)b * HW_ * D_;
    const float rx = ref_xy[(size_t)bt * 2 + 0];
    const float ry = ref_xy[(size_t)bt * 2 + 1];

    const float* pr = g_proj + (size_t)bt * NQ_;

    float wv = -INFINITY, ox = 0.f, oy = 0.f;
    if (lane < P_) {
        wv = pr[256 + h * P_ + lane];
        ox = pr[(h * P_ + lane) * 2 + 0];
        oy = pr[(h * P_ + lane) * 2 + 1];
    }
    float m = wv;
    #pragma unroll
    for (int o = 8; o >= 1; o >>= 1) m = fmaxf(m, __shfl_xor_sync(0xffffffffu, m, o));
    float e = (lane < P_) ? __expf(wv - m) : 0.f;
    float s = e;
    #pragma unroll
    for (int o = 8; o >= 1; o >>= 1) s += __shfl_xor_sync(0xffffffffu, s, o);
    const float aw = (lane < P_) ? (e / s) : 0.f;

    const float ix = (rx + RADIUS_ * ox) * (float)(WF_ - 1);
    const float iy = (ry + RADIUS_ * oy) * (float)(HF_ - 1);
    const float fx0 = floorf(ix), fy0 = floorf(iy);
    const int   x0 = (int)fx0,   y0 = (int)fy0;
    const float fx = ix - fx0,   fy = iy - fy0;

    int   idxc[4];
    float wc[4];
    {
        const int x1 = x0 + 1, y1 = y0 + 1;
        const int xs[4] = {x0, x1, x0, x1};
        const int ys[4] = {y0, y0, y1, y1};
        const float ww[4] = {(1.f - fx) * (1.f - fy), fx * (1.f - fy),
                             (1.f - fx) * fy,         fx * fy};
        #pragma unroll
        for (int c = 0; c < 4; c++) {
            const bool valid = (xs[c] >= 0) & (xs[c] < WF_) & (ys[c] >= 0) & (ys[c] < HF_);
            const int xc = min(max(xs[c], 0), WF_ - 1);
            const int yc = min(max(ys[c], 0), HF_ - 1);
            idxc[c] = yc * WF_ + xc;
            wc[c]   = valid ? (ww[c] * aw) : 0.f;
        }
    }

    float acc0 = 0.f, acc1 = 0.f;
    const int hbase = h * DH_;
    #pragma unroll 4
    for (int p = 0; p < P_; p++) {
        #pragma unroll
        for (int c = 0; c < 4; c++) {
            const int   idx = __shfl_sync(0xffffffffu, idxc[c], p);
            const float w   = __shfl_sync(0xffffffffu, wc[c],   p);
            if (w != 0.f) {
                const float* vp = vb + (size_t)idx * D_ + hbase;
                acc0 += w * vp[lane];
                acc1 += w * vp[lane + 32];
            }
        }
    }
    float* cp = g_ctx + (size_t)bt * D_ + hbase;
    cp[lane]      = acc0;
    cp[lane + 32] = acc1;
}

// ============================================================
extern "C" void kernel_launch(void* const* d_in, const int* in_sizes, int n_in,
                              void* d_out, int out_size)
{
    const float* q      = (const float*)d_in[0];
    const float* fmap   = (const float*)d_in[1];
    const float* ref_xy = (const float*)d_in[2];
    const float* Wv     = (const float*)d_in[3];
    const float* W_off  = (const float*)d_in[4];
    const float* b_off  = (const float*)d_in[5];
    const float* W_w    = (const float*)d_in[6];
    const float* b_w    = (const float*)d_in[7];
    const float* W_out  = (const float*)d_in[8];
    const float* b_out  = (const float*)d_in[9];
    float* out = (float*)d_out;

    float *v, *proj, *ctx, *fmapT, *WvT, *WoutT, *WqT, *bq;
    cudaGetSymbolAddress((void**)&v,     g_v);
    cudaGetSymbolAddress((void**)&proj,  g_proj);
    cudaGetSymbolAddress((void**)&ctx,   g_ctx);
    cudaGetSymbolAddress((void**)&fmapT, g_fmapT);
    cudaGetSymbolAddress((void**)&WvT,   g_WvT);
    cudaGetSymbolAddress((void**)&WoutT, g_WoutT);
    cudaGetSymbolAddress((void**)&WqT,   g_WqT);
    cudaGetSymbolAddress((void**)&bq,    g_bq);

    cudaFuncSetAttribute(gemm_bf16x3, cudaFuncAttributeMaxDynamicSharedMemorySize, GSMEM);

    // L1: fmap [B,C,HW] -> fmapT [B,HW,C]
    transpose_kernel<<<dim3(HW_ / 32, C_ / 32, B_), dim3(32, 8)>>>(fmap, fmapT, C_, HW_);
    // L2: weight transposes + bias concat
    prep_weights<<<dim3(16, 16, 4), dim3(32, 8)>>>(Wv, W_out, W_off, W_w, b_off, b_w);

    // L3: v[b] = fmapT[b] @ Wv
    gemm_bf16x3<<<dim3(HW_ / 128, D_ / 128, B_), 512, GSMEM>>>(
        fmapT, WvT, (const float*)0, v, D_, C_, (size_t)HW_ * C_, (size_t)HW_ * D_);

    // L4: proj = q @ [W_off|W_w] + bias
    gemm_bf16x3<<<dim3(M_BT / 128, NQ_ / 128, 1), 512, GSMEM>>>(
        q, WqT, bq, proj, NQ_, D_, 0, 0);

    // L5: softmax + bilinear gather -> ctx
    sample_kernel<<<M_BT, H_ * 32>>>(ref_xy);

    // L6: out = ctx @ W_out + b_out   (<- ncu -s 5 -c 1 captures this)
    gemm_bf16x3<<<dim3(M_BT / 128, D_ / 128, 1), 512, GSMEM>>>(
        ctx, WoutT, b_out, out, D_, D_, 0, 0);
}

// round 11
// speedup vs baseline: 2.0265x; 1.1235x over previous
#include <cuda_runtime.h>
#include <cuda_bf16.h>
#include <math.h>
#include <stdint.h>

#define B_  4
#define T_  2048
#define D_  512
#define H_  8
#define P_  16
#define DH_ 64
#define C_  512
#define HF_ 64
#define WF_ 64
#define HW_ (HF_*WF_)
#define RADIUS_ 0.08f
#define M_BT (B_*T_)
#define NQ_ (H_*P_*2 + H_*P_)

// ---- scratch ----
__device__ float g_v    [(size_t)B_*HW_*D_];
__device__ float g_proj [(size_t)M_BT*NQ_];
__device__ float g_ctx  [(size_t)M_BT*D_];
__device__ float g_fmapT[(size_t)B_*HW_*C_];
__device__ float g_WvT  [(size_t)D_*C_];
__device__ float g_WoutT[(size_t)D_*D_];
__device__ float g_WqT  [(size_t)NQ_*D_];
__device__ float g_bq   [NQ_];

// ============================================================
// fmap transpose: [B][C][HW] -> [B][HW][C]
// ============================================================
__global__ void transpose_kernel(const float* __restrict__ in, float* __restrict__ out,
                                 int R, int C) {
    __shared__ float tile[32][33];
    const size_t bo = (size_t)blockIdx.z * R * C;
    const int c0 = blockIdx.x * 32, r0 = blockIdx.y * 32;
    const int tx = threadIdx.x, ty = threadIdx.y;
    #pragma unroll
    for (int i = 0; i < 32; i += 8)
        tile[ty + i][tx] = in[bo + (size_t)(r0 + ty + i) * C + c0 + tx];
    __syncthreads();
    #pragma unroll
    for (int i = 0; i < 32; i += 8)
        out[bo + (size_t)(c0 + ty + i) * R + r0 + tx] = tile[tx][ty + i];
}

// ============================================================
// Weight transposes + bias concat (one launch)
// ============================================================
__global__ void prep_weights(const float* __restrict__ Wv,  const float* __restrict__ Wout,
                             const float* __restrict__ Woff, const float* __restrict__ Ww,
                             const float* __restrict__ boff, const float* __restrict__ bw)
{
    __shared__ float tile[32][33];
    const int z = blockIdx.z;
    const float* in; float* out; int Ccols;
    if      (z == 0) { in = Wv;   out = g_WvT;            Ccols = 512; }
    else if (z == 1) { in = Wout; out = g_WoutT;          Ccols = 512; }
    else if (z == 2) { in = Woff; out = g_WqT;            Ccols = 256; }
    else             { in = Ww;   out = g_WqT + 256 * D_; Ccols = 128; }
    const int R = 512;
    const int tx = threadIdx.x, ty = threadIdx.y;

    if (z == 3 && blockIdx.x == 0 && blockIdx.y == 0) {
        const int idx0 = ty * 32 + tx;
        for (int i = idx0; i < NQ_; i += 256)
            g_bq[i] = (i < 256) ? boff[i] : bw[i - 256];
    }

    const int c0 = blockIdx.x * 32, r0 = blockIdx.y * 32;
    if (c0 >= Ccols) return;
    #pragma unroll
    for (int i = 0; i < 32; i += 8)
        tile[ty + i][tx] = in[(size_t)(r0 + ty + i) * Ccols + c0 + tx];
    __syncthreads();
    #pragma unroll
    for (int i = 0; i < 32; i += 8)
        out[(size_t)(c0 + ty + i) * R + r0 + tx] = tile[tx][ty + i];
}

// ============================================================
// bf16x3 split GEMM, 256 threads (8 warps, 4m x 2n), warp tile 32x32.
// CTA tile 128(M) x 64(N), k-chunk 32. 2 CTAs/SM (regs<=128, smem 60KB).
// Pipelined iteration:
//   LDG(i+1) -> LDSM kk0 -> MMA kk0 -> LDSM kk1 -> STS(i+1) -> MMA kk1 -> bar
// ============================================================
#define KC  32
#define KPB 40
#define SSTA (128 * KPB)            // A array tile (bf16 elems)
#define SSTB (64 * KPB)             // B array tile
#define STG (2 * SSTA + 2 * SSTB)   // per-stage elems: A_hi, A_lo, B_hi, B_lo
#define OFF_AH 0
#define OFF_AL SSTA
#define OFF_BH (2 * SSTA)
#define OFF_BL (2 * SSTA + SSTB)
#define GSMEM (2 * STG * 2)         // bytes = 61440

__device__ __forceinline__ void cvt_split4(const float4 v, uint32_t& h01, uint32_t& h23,
                                           uint32_t& l01, uint32_t& l23) {
    __nv_bfloat16 h0 = __float2bfloat16(v.x);
    __nv_bfloat16 h1 = __float2bfloat16(v.y);
    __nv_bfloat16 h2 = __float2bfloat16(v.z);
    __nv_bfloat16 h3 = __float2bfloat16(v.w);
    __nv_bfloat16 l0 = __float2bfloat16(v.x - __bfloat162float(h0));
    __nv_bfloat16 l1 = __float2bfloat16(v.y - __bfloat162float(h1));
    __nv_bfloat16 l2 = __float2bfloat16(v.z - __bfloat162float(h2));
    __nv_bfloat16 l3 = __float2bfloat16(v.w - __bfloat162float(h3));
    __nv_bfloat162 H01 = {h0, h1}, H23 = {h2, h3}, L01 = {l0, l1}, L23 = {l2, l3};
    h01 = *(uint32_t*)&H01; h23 = *(uint32_t*)&H23;
    l01 = *(uint32_t*)&L01; l23 = *(uint32_t*)&L23;
}

#define MMA_BF16(acc, a, b) \
    asm volatile( \
        "mma.sync.aligned.m16n8k16.row.col.f32.bf16.bf16.f32 " \
        "{%0,%1,%2,%3}, {%4,%5,%6,%7}, {%8,%9}, {%0,%1,%2,%3};" \
        : "+f"((acc)[0]), "+f"((acc)[1]), "+f"((acc)[2]), "+f"((acc)[3]) \
        : "r"((a)[0]), "r"((a)[1]), "r"((a)[2]), "r"((a)[3]), \
          "r"((b)[0]), "r"((b)[1]))

#define LDM_X4(r, addr) \
    asm volatile("ldmatrix.sync.aligned.m8n8.x4.shared.b16 {%0,%1,%2,%3}, [%4];" \
        : "=r"((r)[0]), "=r"((r)[1]), "=r"((r)[2]), "=r"((r)[3]) : "r"(addr))
#define LDM_X2(r, addr) \
    asm volatile("ldmatrix.sync.aligned.m8n8.x2.shared.b16 {%0,%1}, [%2];" \
        : "=r"((r)[0]), "=r"((r)[1]) : "r"(addr))

__global__ void __launch_bounds__(256, 2) gemm_bf16x3(
    const float* __restrict__ A, const float* __restrict__ BT,
    const float* __restrict__ bias, float* __restrict__ Cout,
    int N, int K, size_t a_bstride, size_t c_bstride)
{
    extern __shared__ __align__(16) __nv_bfloat16 smem[];

    const int tid = threadIdx.x;
    const int warp = tid >> 5, lane = tid & 31;
    const int g = lane >> 2, t = lane & 3;
    const int warpM = (warp >> 1) * 32;     // 0,32,64,96
    const int warpN = (warp & 1) * 32;      // 0,32
    const int m0 = blockIdx.x * 128, n0 = blockIdx.y * 64;
    const float* Ab = A + blockIdx.z * a_bstride;
    float* Cb = Cout + blockIdx.z * c_bstride;

    const int lrow = tid >> 3;              // 0..31 (+32 per pass)
    const int lkq  = (tid & 7) << 2;        // 0,4,...,28

    const int aRow = (lane & 7) + ((lane >> 3) & 1) * 8;
    const int aK8  = (lane >> 4) * 8;
    const int bRow = lane & 7;
    const int bK8  = ((lane >> 3) & 1) * 8;

    const uint32_t smem_base = (uint32_t)__cvta_generic_to_shared(smem);
    const uint32_t aLaneOff = (uint32_t)((warpM + aRow) * KPB + aK8) * 2;
    const uint32_t bLaneOff = (uint32_t)((warpN + bRow) * KPB + bK8) * 2;

    float acc[2][4][4];
    #pragma unroll
    for (int a = 0; a < 2; a++)
        #pragma unroll
        for (int b = 0; b < 4; b++)
            #pragma unroll
            for (int c = 0; c < 4; c++) acc[a][b][c] = 0.f;

    const int ntiles = K / KC;
    float4 pa[4], pb[2];

    // prologue: tile 0 -> stage 0
    #pragma unroll
    for (int j = 0; j < 4; j++)
        pa[j] = __ldg((const float4*)(Ab + (size_t)(m0 + lrow + j * 32) * K + lkq));
    #pragma unroll
    for (int j = 0; j < 2; j++)
        pb[j] = __ldg((const float4*)(BT + (size_t)(n0 + lrow + j * 32) * K + lkq));
    {
        __nv_bfloat16* st = smem;
        #pragma unroll
        for (int j = 0; j < 4; j++) {
            const int off = (lrow + j * 32) * KPB + lkq;
            uint32_t h01, h23, l01, l23;
            cvt_split4(pa[j], h01, h23, l01, l23);
            *(uint2*)(st + OFF_AH + off) = make_uint2(h01, h23);
            *(uint2*)(st + OFF_AL + off) = make_uint2(l01, l23);
        }
        #pragma unroll
        for (int j = 0; j < 2; j++) {
            const int off = (lrow + j * 32) * KPB + lkq;
            uint32_t h01, h23, l01, l23;
            cvt_split4(pb[j], h01, h23, l01, l23);
            *(uint2*)(st + OFF_BH + off) = make_uint2(h01, h23);
            *(uint2*)(st + OFF_BL + off) = make_uint2(l01, l23);
        }
    }
    __syncthreads();

    int cur = 0;
    for (int i = 0; i < ntiles; i++) {
        // 1. prefetch tile i+1 from global
        if (i + 1 < ntiles) {
            const int k0 = (i + 1) * KC;
            #pragma unroll
            for (int j = 0; j < 4; j++)
                pa[j] = __ldg((const float4*)(Ab + (size_t)(m0 + lrow + j * 32) * K + k0 + lkq));
            #pragma unroll
            for (int j = 0; j < 2; j++)
                pb[j] = __ldg((const float4*)(BT + (size_t)(n0 + lrow + j * 32) * K + k0 + lkq));
        }

        const uint32_t stg = smem_base + (uint32_t)(cur * STG) * 2;
        const uint32_t AhB = stg + aLaneOff;
        const uint32_t AlB = AhB + OFF_AL * 2;
        const uint32_t BhB = stg + OFF_BH * 2 + bLaneOff;
        const uint32_t BlB = stg + OFF_BL * 2 + bLaneOff;

        uint32_t ah[2][4], al[2][4], bh[4][2], bl[4][2];

        // 2. LDSM kk0
        #pragma unroll
        for (int mt = 0; mt < 2; mt++) {
            const uint32_t mo = (uint32_t)(mt * 16 * KPB) * 2;
            LDM_X4(ah[mt], AhB + mo);
            LDM_X4(al[mt], AlB + mo);
        }
        #pragma unroll
        for (int nt = 0; nt < 4; nt++) {
            const uint32_t no = (uint32_t)(nt * 8 * KPB) * 2;
            LDM_X2(bh[nt], BhB + no);
            LDM_X2(bl[nt], BlB + no);
        }
        // 3. MMA kk0
        #pragma unroll
        for (int mt = 0; mt < 2; mt++)
            #pragma unroll
            for (int nt = 0; nt < 4; nt++) {
                MMA_BF16(acc[mt][nt], ah[mt], bh[nt]);
                MMA_BF16(acc[mt][nt], ah[mt], bl[nt]);
                MMA_BF16(acc[mt][nt], al[mt], bh[nt]);
            }

        // 4. LDSM kk1
        uint32_t ah1[2][4], al1[2][4], bh1[4][2], bl1[4][2];
        #pragma unroll
        for (int mt = 0; mt < 2; mt++) {
            const uint32_t mo = (uint32_t)(mt * 16 * KPB) * 2 + 32;
            LDM_X4(ah1[mt], AhB + mo);
            LDM_X4(al1[mt], AlB + mo);
        }
        #pragma unroll
        for (int nt = 0; nt < 4; nt++) {
            const uint32_t no = (uint32_t)(nt * 8 * KPB) * 2 + 32;
            LDM_X2(bh1[nt], BhB + no);
            LDM_X2(bl1[nt], BlB + no);
        }

        // 5. store tile i+1 into other stage
        if (i + 1 < ntiles) {
            __nv_bfloat16* st = smem + (cur ^ 1) * STG;
            #pragma unroll
            for (int j = 0; j < 4; j++) {
                const int off = (lrow + j * 32) * KPB + lkq;
                uint32_t h01, h23, l01, l23;
                cvt_split4(pa[j], h01, h23, l01, l23);
                *(uint2*)(st + OFF_AH + off) = make_uint2(h01, h23);
                *(uint2*)(st + OFF_AL + off) = make_uint2(l01, l23);
            }
            #pragma unroll
            for (int j = 0; j < 2; j++) {
                const int off = (lrow + j * 32) * KPB + lkq;
                uint32_t h01, h23, l01, l23;
                cvt_split4(pb[j], h01, h23, l01, l23);
                *(uint2*)(st + OFF_BH + off) = make_uint2(h01, h23);
                *(uint2*)(st + OFF_BL + off) = make_uint2(l01, l23);
            }
        }

        // 6. MMA kk1 (drains while we hit the barrier / next LDSM)
        #pragma unroll
        for (int mt = 0; mt < 2; mt++)
            #pragma unroll
            for (int nt = 0; nt < 4; nt++) {
                MMA_BF16(acc[mt][nt], ah1[mt], bh1[nt]);
                MMA_BF16(acc[mt][nt], ah1[mt], bl1[nt]);
                MMA_BF16(acc[mt][nt], al1[mt], bh1[nt]);
            }

        __syncthreads();
        cur ^= 1;
    }

    #pragma unroll
    for (int mt = 0; mt < 2; mt++) {
        const int r0 = m0 + warpM + mt * 16 + g;
        #pragma unroll
        for (int nt = 0; nt < 4; nt++) {
            const int cc = n0 + warpN + nt * 8 + 2 * t;
            float b0 = bias ? bias[cc] : 0.f;
            float b1 = bias ? bias[cc + 1] : 0.f;
            float2 o0 = make_float2(acc[mt][nt][0] + b0, acc[mt][nt][1] + b1);
            float2 o1 = make_float2(acc[mt][nt][2] + b0, acc[mt][nt][3] + b1);
            *(float2*)(Cb + (size_t)r0 * N + cc)       = o0;
            *(float2*)(Cb + (size_t)(r0 + 8) * N + cc) = o1;
        }
    }
}

// ============================================================
// Softmax + bilinear gather
// ============================================================
__global__ void sample_kernel(const float* __restrict__ ref_xy)
{
    const int bt = blockIdx.x;
    const int b  = bt >> 11;
    const int h  = threadIdx.x >> 5;
    const int lane = threadIdx.x & 31;

    const float* vb = g_v + (size_t)b * HW_ * D_;
    const float rx = ref_xy[(size_t)bt * 2 + 0];
    const float ry = ref_xy[(size_t)bt * 2 + 1];

    const float* pr = g_proj + (size_t)bt * NQ_;

    float wv = -INFINITY, ox = 0.f, oy = 0.f;
    if (lane < P_) {
        wv = pr[256 + h * P_ + lane];
        ox = pr[(h * P_ + lane) * 2 + 0];
        oy = pr[(h * P_ + lane) * 2 + 1];
    }
    float m = wv;
    #pragma unroll
    for (int o = 8; o >= 1; o >>= 1) m = fmaxf(m, __shfl_xor_sync(0xffffffffu, m, o));
    float e = (lane < P_) ? __expf(wv - m) : 0.f;
    float s = e;
    #pragma unroll
    for (int o = 8; o >= 1; o >>= 1) s += __shfl_xor_sync(0xffffffffu, s, o);
    const float aw = (lane < P_) ? (e / s) : 0.f;

    const float ix = (rx + RADIUS_ * ox) * (float)(WF_ - 1);
    const float iy = (ry + RADIUS_ * oy) * (float)(HF_ - 1);
    const float fx0 = floorf(ix), fy0 = floorf(iy);
    const int   x0 = (int)fx0,   y0 = (int)fy0;
    const float fx = ix - fx0,   fy = iy - fy0;

    int   idxc[4];
    float wc[4];
    {
        const int x1 = x0 + 1, y1 = y0 + 1;
        const int xs[4] = {x0, x1, x0, x1};
        const int ys[4] = {y0, y0, y1, y1};
        const float ww[4] = {(1.f - fx) * (1.f - fy), fx * (1.f - fy),
                             (1.f - fx) * fy,         fx * fy};
        #pragma unroll
        for (int c = 0; c < 4; c++) {
            const bool valid = (xs[c] >= 0) & (xs[c] < WF_) & (ys[c] >= 0) & (ys[c] < HF_);
            const int xc = min(max(xs[c], 0), WF_ - 1);
            const int yc = min(max(ys[c], 0), HF_ - 1);
            idxc[c] = yc * WF_ + xc;
            wc[c]   = valid ? (ww[c] * aw) : 0.f;
        }
    }

    float acc0 = 0.f, acc1 = 0.f;
    const int hbase = h * DH_;
    #pragma unroll 4
    for (int p = 0; p < P_; p++) {
        #pragma unroll
        for (int c = 0; c < 4; c++) {
            const int   idx = __shfl_sync(0xffffffffu, idxc[c], p);
            const float w   = __shfl_sync(0xffffffffu, wc[c],   p);
            if (w != 0.f) {
                const float* vp = vb + (size_t)idx * D_ + hbase;
                acc0 += w * vp[lane];
                acc1 += w * vp[lane + 32];
            }
        }
    }
    float* cp = g_ctx + (size_t)bt * D_ + hbase;
    cp[lane]      = acc0;
    cp[lane + 32] = acc1;
}

// ============================================================
extern "C" void kernel_launch(void* const* d_in, const int* in_sizes, int n_in,
                              void* d_out, int out_size)
{
    const float* q      = (const float*)d_in[0];
    const float* fmap   = (const float*)d_in[1];
    const float* ref_xy = (const float*)d_in[2];
    const float* Wv     = (const float*)d_in[3];
    const float* W_off  = (const float*)d_in[4];
    const float* b_off  = (const float*)d_in[5];
    const float* W_w    = (const float*)d_in[6];
    const float* b_w    = (const float*)d_in[7];
    const float* W_out  = (const float*)d_in[8];
    const float* b_out  = (const float*)d_in[9];
    float* out = (float*)d_out;

    float *v, *proj, *ctx, *fmapT, *WvT, *WoutT, *WqT, *bq;
    cudaGetSymbolAddress((void**)&v,     g_v);
    cudaGetSymbolAddress((void**)&proj,  g_proj);
    cudaGetSymbolAddress((void**)&ctx,   g_ctx);
    cudaGetSymbolAddress((void**)&fmapT, g_fmapT);
    cudaGetSymbolAddress((void**)&WvT,   g_WvT);
    cudaGetSymbolAddress((void**)&WoutT, g_WoutT);
    cudaGetSymbolAddress((void**)&WqT,   g_WqT);
    cudaGetSymbolAddress((void**)&bq,    g_bq);

    cudaFuncSetAttribute(gemm_bf16x3, cudaFuncAttributeMaxDynamicSharedMemorySize, GSMEM);

    // L1: fmap [B,C,HW] -> fmapT [B,HW,C]
    transpose_kernel<<<dim3(HW_ / 32, C_ / 32, B_), dim3(32, 8)>>>(fmap, fmapT, C_, HW_);
    // L2: weight transposes + bias concat
    prep_weights<<<dim3(16, 16, 4), dim3(32, 8)>>>(Wv, W_out, W_off, W_w, b_off, b_w);

    // L3: v[b] = fmapT[b] @ Wv
    gemm_bf16x3<<<dim3(HW_ / 128, D_ / 64, B_), 256, GSMEM>>>(
        fmapT, WvT, (const float*)0, v, D_, C_, (size_t)HW_ * C_, (size_t)HW_ * D_);

    // L4: proj = q @ [W_off|W_w] + bias
    gemm_bf16x3<<<dim3(M_BT / 128, NQ_ / 64, 1), 256, GSMEM>>>(
        q, WqT, bq, proj, NQ_, D_, 0, 0);

    // L5: softmax + bilinear gather -> ctx
    sample_kernel<<<M_BT, H_ * 32>>>(ref_xy);

    // L6: out = ctx @ W_out + b_out   (<- ncu -s 5 -c 1 captures this)
    gemm_bf16x3<<<dim3(M_BT / 128, D_ / 64, 1), 256, GSMEM>>>(
        ctx, WoutT, b_out, out, D_, D_, 0, 0);
}